// round 9
// baseline (speedup 1.0000x reference)
#include <cuda_runtime.h>

#define S_GRID 28
#define SS 784            // 28*28
#define NC 80
#define BB 2
#define MAXB 50
#define PRED_C 90         // BB*5 + NC
#define NSWEEP 368        // 512 + 368 = 880 blocks = one RF-limited wave

__device__ float g_partial[2048];
__device__ int   g_count = 0;

__device__ __forceinline__ float bce_term(float x, unsigned gbit) {
    float g = gbit ? 1.0f : 0.0f;
    return fmaxf(x, 0.0f) - x * g + log1pf(__expf(-fabsf(x)));
}

__global__ __launch_bounds__(256, 6) void yolo_loss_kernel(
    const float* __restrict__ pred,
    const float* __restrict__ tgt,
    float* __restrict__ out,
    int batch)
{
    const int bid = blockIdx.x;
    const int tid = threadIdx.x;
    const float cell = 1.0f / 28.0f;

    float partial = 0.0f;

    if (bid >= batch) {
        // ============ role A: flat noobj confidence sweep (368 blocks) ============
        const long total  = (long)batch * SS;
        const long stride = (long)NSWEEP * 256;
        long c = (long)(bid - batch) * 256 + tid;
        float a0 = 0.f, a1 = 0.f, a2 = 0.f, a3 = 0.f;
        for (; c + 3 * stride < total; c += 4 * stride) {
            const float* p0 = pred + (c             ) * PRED_C;
            const float* p1 = pred + (c +     stride) * PRED_C;
            const float* p2 = pred + (c + 2 * stride) * PRED_C;
            const float* p3 = pred + (c + 3 * stride) * PRED_C;
            float x0 = __ldg(p0 + 4), y0 = __ldg(p0 + 9);
            float x1 = __ldg(p1 + 4), y1 = __ldg(p1 + 9);
            float x2 = __ldg(p2 + 4), y2 = __ldg(p2 + 9);
            float x3 = __ldg(p3 + 4), y3 = __ldg(p3 + 9);
            a0 += x0 * x0 + y0 * y0;
            a1 += x1 * x1 + y1 * y1;
            a2 += x2 * x2 + y2 * y2;
            a3 += x3 * x3 + y3 * y3;
        }
        for (; c < total; c += stride) {
            const float* pp = pred + c * PRED_C;
            float x = __ldg(pp + 4), y = __ldg(pp + 9);
            a0 += x * x + y * y;
        }
        partial = 0.1f * ((a0 + a1) + (a2 + a3));
    } else {
        // ============ role B: per-batch target/object losses (512 blocks) =========
        const int b = bid;
        const float* pb = pred + (size_t)b * SS * PRED_C;

        __shared__ float  s_traw[2 * MAXB * 5 / 2];  // 250 floats staged
        __shared__ int    s_cell[MAXB];
        __shared__ float  s_best[MAXB];
        __shared__ float4 s_gbox[MAXB];
        __shared__ float4 s_pbox[MAXB];
        __shared__ float  s_pconf[MAXB];
        __shared__ int    s_cid[MAXB];
        __shared__ unsigned char s_win[MAXB];
        __shared__ int    s_obj[MAXB];
        __shared__ int    s_nobj;
        __shared__ unsigned s_mask[MAXB][3];

        // coalesced float2 stage of the 250 target floats (tgt base 8-aligned)
        if (tid < 125) {
            const float2* tt2 =
                reinterpret_cast<const float2*>(tgt + (size_t)b * MAXB * 5);
            float2 v = __ldg(tt2 + tid);
            s_traw[2 * tid]     = v.x;
            s_traw[2 * tid + 1] = v.y;
        }
        __syncthreads();

        // phase 1: per-target precompute; stash responsible pred box in SMEM
        if (tid < MAXB) {
            float tcls = s_traw[tid * 5 + 0];
            if (tcls >= 0.0f) {
                float tcx = s_traw[tid * 5 + 1], tcy = s_traw[tid * 5 + 2];
                float tw  = s_traw[tid * 5 + 3], th  = s_traw[tid * 5 + 4];
                int ci  = min(max((int)tcls, 0), NC - 1);
                int col = min((int)(tcx / cell), S_GRID - 1);
                int row = min((int)(tcy / cell), S_GRID - 1);
                int cc  = row * S_GRID + col;
                s_cell[tid] = cc;
                s_cid[tid]  = ci;
                s_gbox[tid] = make_float4(tcx / cell - (float)col,
                                          tcy / cell - (float)row, tw, th);
                const float2* pp2 =
                    reinterpret_cast<const float2*>(pb + (size_t)cc * PRED_C);
                float2 v0 = __ldg(pp2 + 0);   // x0 y0
                float2 v1 = __ldg(pp2 + 1);   // w0 h0
                float2 v2 = __ldg(pp2 + 2);   // c0 x1
                float2 v3 = __ldg(pp2 + 3);   // y1 w1
                float2 v4 = __ldg(pp2 + 4);   // h1 c1
                float bxj[2] = {v0.x, v2.y};
                float byj[2] = {v0.y, v3.x};
                float bwj[2] = {v1.x, v3.y};
                float bhj[2] = {v1.y, v4.x};
                float bcj[2] = {v2.x, v4.y};

                float gx1 = tcx - tw * .5f, gy1 = tcy - th * .5f;
                float gx2 = tcx + tw * .5f, gy2 = tcy + th * .5f;
                float garea = fmaxf(gx2 - gx1, 0.f) * fmaxf(gy2 - gy1, 0.f);
                float iou[2];
                #pragma unroll
                for (int j = 0; j < 2; j++) {
                    float px = (bxj[j] + (float)col) * cell;
                    float py = (byj[j] + (float)row) * cell;
                    float pw = bwj[j], ph = bhj[j];
                    float px1 = px - pw * .5f, py1 = py - ph * .5f;
                    float px2 = px + pw * .5f, py2 = py + ph * .5f;
                    float iw = fmaxf(fminf(px2, gx2) - fmaxf(px1, gx1), 0.f);
                    float ih = fmaxf(fminf(py2, gy2) - fmaxf(py1, gy1), 0.f);
                    float inter = iw * ih;
                    float uni = fmaxf(px2 - px1, 0.f) * fmaxf(py2 - py1, 0.f)
                              + garea - inter;
                    iou[j] = inter / (uni + 1e-6f);
                }
                int r = (iou[1] > iou[0]) ? 1 : 0;   // first-index tie break
                s_best[tid]  = fmaxf(iou[0], iou[1]);
                s_pbox[tid]  = make_float4(bxj[r], byj[r], bwj[r], bhj[r]);
                s_pconf[tid] = bcj[r];
            } else {
                s_cell[tid] = -1;
            }
        }
        __syncthreads();

        // winner per cell = first index achieving max best (scan semantics)
        if (tid < MAXB) {
            bool win = (s_cell[tid] >= 0);
            if (win) {
                int myc = s_cell[tid]; float myb = s_best[tid];
                for (int s = 0; s < MAXB; s++) {
                    if (s == tid || s_cell[s] != myc) continue;
                    float ob = s_best[s];
                    if (ob > myb || (ob == myb && s < tid)) { win = false; break; }
                }
            }
            s_win[tid] = win ? 1 : 0;
        }
        __syncthreads();

        // deterministic compaction (warp 0, two ballots)
        if (tid < 32) {
            unsigned lt = (1u << tid) - 1u;
            bool p0 = s_win[tid] != 0;
            unsigned m0 = __ballot_sync(0xffffffffu, p0);
            if (p0) s_obj[__popc(m0 & lt)] = tid;
            int c0 = __popc(m0);
            bool p1 = (tid < MAXB - 32) && (s_win[32 + tid] != 0);
            unsigned m1 = __ballot_sync(0xffffffffu, p1);
            if (p1) s_obj[c0 + __popc(m1 & lt)] = 32 + tid;
            if (tid == 0) s_nobj = c0 + __popc(m1);
        }
        __syncthreads();
        const int nobj = s_nobj;

        // per-winner class masks
        if (tid < nobj) {
            int t = s_obj[tid];
            int myc = s_cell[t];
            unsigned m0 = 0u, m1 = 0u, m2 = 0u;
            for (int s = 0; s < MAXB; s++) {
                if (s_cell[s] == myc) {
                    int ci = s_cid[s];
                    if (ci < 32)      m0 |= 1u << ci;
                    else if (ci < 64) m1 |= 1u << (ci - 32);
                    else              m2 |= 1u << (ci - 64);
                }
            }
            s_mask[tid][0] = m0; s_mask[tid][1] = m1; s_mask[tid][2] = m2;
        }
        __syncthreads();

        float acc_obj = 0.f, acc_coord = 0.f, acc_cls = 0.f, acc_corr = 0.f;

        // CIoU + obj conf + noobj correction: 100% SMEM
        for (int i = tid; i < nobj; i += 256) {
            int t = s_obj[i];
            int c = s_cell[t];
            float4 p = s_pbox[t];
            float bc = s_pconf[t];
            acc_corr += bc * bc;
            float d = bc - s_best[t];
            acc_obj += d * d;

            int row = c / S_GRID, col = c % S_GRID;
            float4 g = s_gbox[t];
            float px = (p.x + (float)col) * cell, py = (p.y + (float)row) * cell;
            float pw = fabsf(p.z), ph = fabsf(p.w);
            float gx = (g.x + (float)col) * cell, gy = (g.y + (float)row) * cell;
            float gw = g.z, gh = g.w;

            float px1 = px - pw * .5f, py1 = py - ph * .5f;
            float px2 = px + pw * .5f, py2 = py + ph * .5f;
            float gx1 = gx - gw * .5f, gy1 = gy - gh * .5f;
            float gx2 = gx + gw * .5f, gy2 = gy + gh * .5f;
            float iw = fmaxf(fminf(px2, gx2) - fmaxf(px1, gx1), 0.f);
            float ih = fmaxf(fminf(py2, gy2) - fmaxf(py1, gy1), 0.f);
            float inter = iw * ih;
            float ap = fmaxf(px2 - px1, 0.f) * fmaxf(py2 - py1, 0.f);
            float ag = fmaxf(gx2 - gx1, 0.f) * fmaxf(gy2 - gy1, 0.f);
            float uni = ap + ag - inter;
            float iou = inter / (uni + 1e-7f);
            float rho2 = (px - gx) * (px - gx) + (py - gy) * (py - gy);
            float cw = fmaxf(px2, gx2) - fminf(px1, gx1);
            float ch = fmaxf(py2, gy2) - fminf(py1, gy1);
            float c2 = cw * cw + ch * ch + 1e-7f;
            float dv = atanf(gw / (gh + 1e-7f)) - atanf(pw / (ph + 1e-7f));
            float v = 0.40528473456935108577f * dv * dv;   // 4/pi^2
            float alpha = v / (1.0f - iou + v + 1e-7f);
            acc_coord += 1.0f - iou + rho2 / c2 + alpha * v;
        }

        // class BCE: float4 loads (alignment: byte 360c+40 is 16-aligned iff c odd)
        // 21 slots per cell: odd c -> 20x float4; even c -> f2 + 19x float4 + f2
        for (int idx = tid; idx < nobj * 21; idx += 256) {
            int i = idx / 21;
            int slot = idx - i * 21;
            int c = s_cell[s_obj[i]];
            const char* rowb = reinterpret_cast<const char*>(pb + (size_t)c * PRED_C);
            const unsigned* mk = s_mask[i];
            if (c & 1) {
                if (slot < 20) {
                    float4 x4 = __ldg(reinterpret_cast<const float4*>(rowb + 40 + 16 * slot));
                    int k = 4 * slot;
                    acc_cls += bce_term(x4.x, (mk[k >> 5] >> (k & 31)) & 1u);
                    acc_cls += bce_term(x4.y, (mk[(k+1) >> 5] >> ((k+1) & 31)) & 1u);
                    acc_cls += bce_term(x4.z, (mk[(k+2) >> 5] >> ((k+2) & 31)) & 1u);
                    acc_cls += bce_term(x4.w, (mk[(k+3) >> 5] >> ((k+3) & 31)) & 1u);
                }
            } else {
                if (slot == 0) {
                    float2 x2 = __ldg(reinterpret_cast<const float2*>(rowb + 40));
                    acc_cls += bce_term(x2.x, mk[0] & 1u);
                    acc_cls += bce_term(x2.y, (mk[0] >> 1) & 1u);
                } else if (slot < 20) {
                    float4 x4 = __ldg(reinterpret_cast<const float4*>(rowb + 48 + 16 * (slot - 1)));
                    int k = 4 * slot - 2;                  // classes 4slot-2 .. 4slot+1
                    acc_cls += bce_term(x4.x, (mk[k >> 5] >> (k & 31)) & 1u);
                    acc_cls += bce_term(x4.y, (mk[(k+1) >> 5] >> ((k+1) & 31)) & 1u);
                    acc_cls += bce_term(x4.z, (mk[(k+2) >> 5] >> ((k+2) & 31)) & 1u);
                    acc_cls += bce_term(x4.w, (mk[(k+3) >> 5] >> ((k+3) & 31)) & 1u);
                } else {
                    float2 x2 = __ldg(reinterpret_cast<const float2*>(rowb + 40 + 78 * 4));
                    acc_cls += bce_term(x2.x, (mk[2] >> 14) & 1u);   // class 78
                    acc_cls += bce_term(x2.y, (mk[2] >> 15) & 1u);   // class 79
                }
            }
        }

        partial = 5.0f * acc_coord + acc_obj + acc_cls - 0.1f * acc_corr;
    }

    // ---- block reduction: shuffle within warp, fixed-order across warps ----
    __shared__ float s_red[8];
    #pragma unroll
    for (int off = 16; off > 0; off >>= 1)
        partial += __shfl_down_sync(0xffffffffu, partial, off);
    if ((tid & 31) == 0) s_red[tid >> 5] = partial;
    __syncthreads();
    if (tid == 0) {
        float v = ((s_red[0] + s_red[1]) + (s_red[2] + s_red[3]))
                + ((s_red[4] + s_red[5]) + (s_red[6] + s_red[7]));
        g_partial[bid] = v;
        __threadfence();
    }
    __syncthreads();

    // ---- last block: fixed-order final reduction (deterministic) ----
    const int nparts = batch + NSWEEP;
    __shared__ int s_last;
    if (tid == 0) s_last = (atomicAdd(&g_count, 1) == nparts - 1) ? 1 : 0;
    __syncthreads();
    if (s_last) {
        __shared__ float s_fin[256];
        float v = 0.0f;
        for (int i = tid; i < nparts; i += 256) v += g_partial[i];
        s_fin[tid] = v;
        __syncthreads();
        #pragma unroll
        for (int k = 128; k > 0; k >>= 1) {
            if (tid < k) s_fin[tid] += s_fin[tid + k];
            __syncthreads();
        }
        if (tid == 0) {
            out[0] = s_fin[0] / (float)batch;
            g_count = 0;                     // reset for next graph replay
        }
    }
}

extern "C" void kernel_launch(void* const* d_in, const int* in_sizes, int n_in,
                              void* d_out, int out_size)
{
    const float* pred = (const float*)d_in[0];
    const float* tgt  = (const float*)d_in[1];
    int batch = in_sizes[0] / (SS * PRED_C);
    if (batch > 1024) batch = 1024;
    yolo_loss_kernel<<<batch + NSWEEP, 256>>>(pred, tgt, (float*)d_out, batch);
}

// round 10
// speedup vs baseline: 1.3458x; 1.3458x over previous
#include <cuda_runtime.h>

#define S_GRID 28
#define SS 784            // 28*28
#define NC 80
#define BB 2
#define MAXB 50
#define PRED_C 90         // BB*5 + NC

__device__ float g_partial[4096];
__device__ int   g_count = 0;

__global__ __launch_bounds__(256) void yolo_loss_kernel(
    const float* __restrict__ pred,
    const float* __restrict__ tgt,
    float* __restrict__ out,
    int batch)
{
    const int b   = blockIdx.x;
    const int tid = threadIdx.x;

    __shared__ unsigned long long s_key[SS];   // (bits(best)<<32)|(63-t); 0 = empty
    __shared__ float4   s_gtbox[SS];
    __shared__ float    s_bestiou[SS];
    __shared__ int      s_resp[SS];            // winner's best box idx
    __shared__ unsigned s_cls[SS][3];          // 80-bit class mask
    __shared__ int      s_objlist[MAXB + 2];
    __shared__ int      s_nobj;
    __shared__ float    s_red[8];

    const float cell = 1.0f / 28.0f;
    const float* pb = pred + (size_t)b * SS * PRED_C;

    // ---- issue the target loads ASAP (2-deep dependent DRAM chain) ----
    float t0 = 0.f, t1 = 0.f, t2 = 0.f, t3 = 0.f, t4 = -1.f;
    if (tid < MAXB) {
        const float* tt = tgt + ((size_t)b * MAXB + tid) * 5;
        t4 = tt[0]; t0 = tt[1]; t1 = tt[2]; t2 = tt[3]; t3 = tt[4];
    }

    // ---- noobj confidence sweep: ALL loads issued before ANY use (MLP=8) ----
    // cells tid, tid+256, tid+512 always valid; tid+768 valid only for tid<16.
    float x0 = __ldg(pb + (tid        ) * PRED_C + 4);
    float y0 = __ldg(pb + (tid        ) * PRED_C + 9);
    float x1 = __ldg(pb + (tid +  256 ) * PRED_C + 4);
    float y1 = __ldg(pb + (tid +  256 ) * PRED_C + 9);
    float x2 = __ldg(pb + (tid +  512 ) * PRED_C + 4);
    float y2 = __ldg(pb + (tid +  512 ) * PRED_C + 9);
    float x3 = 0.f, y3 = 0.f;
    if (tid < SS - 768) {
        x3 = __ldg(pb + (tid + 768) * PRED_C + 4);
        y3 = __ldg(pb + (tid + 768) * PRED_C + 9);
    }
    float acc_noobj = ((x0 * x0 + y0 * y0) + (x1 * x1 + y1 * y1))
                    + ((x2 * x2 + y2 * y2) + (x3 * x3 + y3 * y3));

    // ---- SMEM init ----
    for (int c = tid; c < SS; c += 256) {
        s_key[c]  = 0ull;
        s_resp[c] = -1;
        s_cls[c][0] = 0u; s_cls[c][1] = 0u; s_cls[c][2] = 0u;
    }
    __syncthreads();

    // ---- per-target precompute + atomicMax race (replaces serial scan) ----
    int   my_cell = -1, my_bestj = 0;
    float my_best = 0.f;
    float4 my_box;
    unsigned long long my_key = 0ull;
    if (tid < MAXB && t4 >= 0.0f) {
        float cx = t0, cy = t1, w = t2, h = t3;
        int ci  = min(max((int)t4, 0), NC - 1);
        int col = min((int)(cx / cell), S_GRID - 1);
        int row = min((int)(cy / cell), S_GRID - 1);
        float cxr = cx / cell - (float)col;
        float cyr = cy / cell - (float)row;
        my_cell = row * S_GRID + col;
        my_box  = make_float4(cxr, cyr, w, h);

        const float* pp = pb + my_cell * PRED_C;
        float gx1 = cx - w * 0.5f, gy1 = cy - h * 0.5f;
        float gx2 = cx + w * 0.5f, gy2 = cy + h * 0.5f;
        float garea = fmaxf(gx2 - gx1, 0.0f) * fmaxf(gy2 - gy1, 0.0f);
        float iou[2];
        #pragma unroll
        for (int j = 0; j < 2; j++) {
            float px = (pp[5*j + 0] + (float)col) * cell;
            float py = (pp[5*j + 1] + (float)row) * cell;
            float pw = pp[5*j + 2], ph = pp[5*j + 3];
            float px1 = px - pw * 0.5f, py1 = py - ph * 0.5f;
            float px2 = px + pw * 0.5f, py2 = py + ph * 0.5f;
            float iw = fmaxf(fminf(px2, gx2) - fmaxf(px1, gx1), 0.0f);
            float ih = fmaxf(fminf(py2, gy2) - fmaxf(py1, gy1), 0.0f);
            float inter = iw * ih;
            float uni = fmaxf(px2 - px1, 0.0f) * fmaxf(py2 - py1, 0.0f)
                      + garea - inter;
            iou[j] = inter / (uni + 1e-6f);
        }
        my_bestj = (iou[1] > iou[0]) ? 1 : 0;      // first-index tie break
        my_best  = fmaxf(iou[0], iou[1]);
        // scan semantics == first index achieving the max best per cell:
        // strictly-greater steals; equal does not. Key orders by (best, -t).
        my_key = ((unsigned long long)__float_as_uint(my_best) << 32)
               | (unsigned long long)(63 - tid);
        atomicMax(&s_key[my_cell], my_key);
        atomicOr(&s_cls[my_cell][ci >> 5], 1u << (ci & 31));
    }
    __syncthreads();

    // winners write their cell state (unique per cell)
    if (my_key != 0ull && s_key[my_cell] == my_key) {
        s_gtbox[my_cell]   = my_box;
        s_bestiou[my_cell] = my_best;
        s_resp[my_cell]    = my_bestj;
    }
    __syncthreads();

    // ---- deterministic compaction of object cells (warp 0 ballot scan) ----
    if (tid < 32) {
        int count = 0;
        #pragma unroll
        for (int cb = 0; cb < SS; cb += 32) {
            int c = cb + tid;
            bool p = (c < SS) && (s_resp[c] >= 0);
            unsigned m = __ballot_sync(0xffffffffu, p);
            if (p) s_objlist[count + __popc(m & ((1u << tid) - 1u))] = c;
            count += __popc(m);
        }
        if (tid == 0) s_nobj = count;
    }
    __syncthreads();
    const int nobj = s_nobj;

    float acc_obj = 0.0f, acc_coord = 0.0f, acc_cls = 0.0f;

    // ---- object cells: CIoU + obj conf + noobj correction ----
    for (int i = tid; i < nobj; i += 256) {
        int c = s_objlist[i];
        const float* pp = pb + c * PRED_C;
        int r = s_resp[c];
        float bx = pp[5*r + 0], by = pp[5*r + 1];
        float bw = pp[5*r + 2], bh = pp[5*r + 3], bc = pp[5*r + 4];
        acc_noobj -= bc * bc;                 // responsible box excluded
        float d = bc - s_bestiou[c];
        acc_obj += d * d;

        int row = c / S_GRID, col = c % S_GRID;
        float4 g = s_gtbox[c];
        float px = (bx + (float)col) * cell, py = (by + (float)row) * cell;
        float pw = fabsf(bw), ph = fabsf(bh);
        float gx = (g.x + (float)col) * cell, gy = (g.y + (float)row) * cell;
        float gw = g.z, gh = g.w;

        float px1 = px - pw * 0.5f, py1 = py - ph * 0.5f;
        float px2 = px + pw * 0.5f, py2 = py + ph * 0.5f;
        float gx1 = gx - gw * 0.5f, gy1 = gy - gh * 0.5f;
        float gx2 = gx + gw * 0.5f, gy2 = gy + gh * 0.5f;
        float iw = fmaxf(fminf(px2, gx2) - fmaxf(px1, gx1), 0.0f);
        float ih = fmaxf(fminf(py2, gy2) - fmaxf(py1, gy1), 0.0f);
        float inter = iw * ih;
        float ap = fmaxf(px2 - px1, 0.0f) * fmaxf(py2 - py1, 0.0f);
        float ag = fmaxf(gx2 - gx1, 0.0f) * fmaxf(gy2 - gy1, 0.0f);
        float uni = ap + ag - inter;
        float iou = inter / (uni + 1e-7f);
        float rho2 = (px - gx) * (px - gx) + (py - gy) * (py - gy);
        float cw = fmaxf(px2, gx2) - fminf(px1, gx1);
        float ch = fmaxf(py2, gy2) - fminf(py1, gy1);
        float c2 = cw * cw + ch * ch + 1e-7f;
        float dv = atanf(gw / (gh + 1e-7f)) - atanf(pw / (ph + 1e-7f));
        float v = 0.40528473456935108577f * dv * dv;   // 4/pi^2
        float alpha = v / (1.0f - iou + v + 1e-7f);
        acc_coord += 1.0f - iou + rho2 / c2 + alpha * v;
    }

    // ---- class BCE over (obj cell, class) pairs ----
    for (int idx = tid; idx < nobj * NC; idx += 256) {
        int i  = idx / NC;
        int cc = idx - i * NC;
        int c  = s_objlist[i];
        float x = __ldg(pb + c * PRED_C + BB * 5 + cc);
        float gflag = ((s_cls[c][cc >> 5] >> (cc & 31)) & 1u) ? 1.0f : 0.0f;
        acc_cls += fmaxf(x, 0.0f) - x * gflag + log1pf(expf(-fabsf(x)));
    }

    // ---- block reduction: shuffle within warp, tree across warps ----
    float total = 5.0f * acc_coord + acc_obj + 0.1f * acc_noobj + acc_cls;
    #pragma unroll
    for (int off = 16; off > 0; off >>= 1)
        total += __shfl_down_sync(0xffffffffu, total, off);
    if ((tid & 31) == 0) s_red[tid >> 5] = total;
    __syncthreads();
    if (tid == 0) {
        float v = ((s_red[0] + s_red[1]) + (s_red[2] + s_red[3]))
                + ((s_red[4] + s_red[5]) + (s_red[6] + s_red[7]));
        g_partial[b] = v;
        __threadfence();
    }
    __syncthreads();

    // ---- last block performs the final deterministic reduction ----
    __shared__ int s_last;
    if (tid == 0) s_last = (atomicAdd(&g_count, 1) == batch - 1) ? 1 : 0;
    __syncthreads();
    if (s_last) {
        // fixed-order tree over g_partial: value is replay-deterministic
        __shared__ float s_fin[256];
        float v = 0.0f;
        for (int i = tid; i < batch; i += 256) v += g_partial[i];
        s_fin[tid] = v;
        __syncthreads();
        #pragma unroll
        for (int k = 128; k > 0; k >>= 1) {
            if (tid < k) s_fin[tid] += s_fin[tid + k];
            __syncthreads();
        }
        if (tid == 0) {
            out[0] = s_fin[0] / (float)batch;
            g_count = 0;                        // reset for next graph replay
        }
    }
}

extern "C" void kernel_launch(void* const* d_in, const int* in_sizes, int n_in,
                              void* d_out, int out_size)
{
    const float* pred = (const float*)d_in[0];
    const float* tgt  = (const float*)d_in[1];
    int batch = in_sizes[0] / (SS * PRED_C);
    if (batch > 4096) batch = 4096;
    yolo_loss_kernel<<<batch, 256>>>(pred, tgt, (float*)d_out, batch);
}